// round 12
// baseline (speedup 1.0000x reference)
#include <cuda_runtime.h>

#define N      4096
#define NFEAT  6
#define NB     4096          // fine value-buckets per feature
#define IB     256           // threads per block
#define NBI    8             // i-blocks (512 i each, 2 per thread)
#define NJ     64            // j-chunks
#define JC     64            // j per chunk

// Pairwise partials (sky_sep, mass_sim) per j-chunk
__device__ float2 g_part2[NJ][N];
// Closed-form per-row sums: 0=dt 1=dpsi 2=dra 3=ddec 4=freq_ov 5=dist_ratio
__device__ float  g_closed[NFEAT][N];

__device__ __forceinline__ float f_ex2(float x) {
    float r; asm("ex2.approx.ftz.f32 %0, %1;" : "=f"(r) : "f"(x)); return r;
}
__device__ __forceinline__ float f_lg2(float x) {
    float r; asm("lg2.approx.ftz.f32 %0, %1;" : "=f"(r) : "f"(x)); return r;
}
__device__ __forceinline__ float f_rcp(float x) {
    float r; asm("rcp.approx.ftz.f32 %0, %1;" : "=f"(r) : "f"(x)); return r;
}
__device__ __forceinline__ float f_sqrt(float x) {
    float r; asm("sqrt.approx.ftz.f32 %0, %1;" : "=f"(r) : "f"(x)); return r;
}

// (ra, dec, mc30) from a 15-float row in smem
__device__ __forceinline__ float3 inv_from_row(const float* q) {
    float m1 = q[0] * 95.0f + 5.0f;
    float m2 = q[1] * 95.0f + 5.0f;
    float mc = f_ex2(0.6f * f_lg2(m1 * m2) - 0.2f * f_lg2(m1 + m2));
    return make_float3(q[3], q[4], mc * (1.0f / 30.0f));
}

// (key,u,w) from a 15-float row in smem
__device__ __forceinline__ void feat_from_row(const float* q, int feat,
                                              float& key, float& u, float& w) {
    if (feat == 0)      { key = q[5]; u = key; w = 0.f; }
    else if (feat == 1) { key = q[7]; u = key; w = 0.f; }
    else if (feat == 2) { key = q[3]; u = key; w = 0.f; }
    else if (feat == 3) { key = q[4]; u = key; w = 0.f; }
    else if (feat == 4) {
        float msum = (q[0] + q[1]) * 95.0f + 10.0f;
        const float C = 3.1739290899557192f;          // 220*log2(e)/100
        float x = C * f_rcp(msum);
        key = x; u = f_ex2(x); w = f_ex2(-x);
    } else {
        float d = q[2] * 2950.0f + 50.0f;
        key = f_lg2(d); u = d; w = f_rcp(d);
    }
}

// exclusive prefix over 256 thread-values (tid order); all threads call.
__device__ __forceinline__ float excl_scan256(float val, float* warpTmp) {
    const int lane = threadIdx.x & 31, wid = threadIdx.x >> 5;
    float incl = val;
    #pragma unroll
    for (int off = 1; off < 32; off <<= 1) {
        float t = __shfl_up_sync(0xFFFFFFFFu, incl, off);
        if (lane >= off) incl += t;
    }
    __syncthreads();
    if (lane == 31) warpTmp[wid] = incl;
    __syncthreads();
    float base = 0.f;
    #pragma unroll
    for (int ww = 0; ww < 8; ++ww)
        base += (ww < wid) ? warpTmp[ww] : 0.f;
    return base + incl - val;
}

// in-place inclusive scan of arr[NB] with 256 threads (16 per thread)
__device__ __forceinline__ void incl_scan4096(float* arr, float* warpTmp) {
    const int base = threadIdx.x * 16;
    float seg = 0.f;
    #pragma unroll
    for (int q = 0; q < 16; ++q) seg += arr[base + q];
    float run = excl_scan256(seg, warpTmp);
    #pragma unroll
    for (int q = 0; q < 16; ++q) { run += arr[base + q]; arr[base + q] = run; }
}

// smem layout: feature path = 32KB buckets + 15KB staging + 64B tmp = 48.2KB
//              pairwise path = 15KB staging + 1KB sj (aliases the front)
#define OFF_STAGE (NB * 8)
#define OFF_WTMP  (NB * 8 + 15360)
#define SMEM_SZ   (NB * 8 + 15360 + 64)

// ---------------------------------------------------------------------------
// Fused kernel: 6 feature blocks + 512 pairwise blocks. No prep kernel.
// ---------------------------------------------------------------------------
__global__ void __launch_bounds__(IB) fused_kernel(const float* __restrict__ p) {
    __shared__ __align__(16) unsigned char smraw[SMEM_SZ];
    const int tid = threadIdx.x;

    if (blockIdx.x < NFEAT) {
        // ============ FEATURE BLOCK: bucketed O(1) closed form ============
        const int feat = blockIdx.x;
        const bool isexp = (feat >= 4);
        float* sA      = (float*)(smraw);             // abs: incl count | exp: incl U
        float* sB      = (float*)(smraw + NB * 4);    // abs: incl U     | exp: incl W
        float* stage   = (float*)(smraw + OFF_STAGE); // 256 rows x 15 floats
        float* warpTmp = (float*)(smraw + OFF_WTMP);

        float lo, scale;
        if      (feat == 4) { lo = 0.01580f; scale = (float)NB / 0.30220f; }
        else if (feat == 5) { lo = 5.64350f; scale = (float)NB / 5.91200f; }
        else                { lo = 0.0f;     scale = (float)NB; }

        for (int q = tid; q < NB; q += IB) { sA[q] = 0.f; sB[q] = 0.f; }

        // stage p coalesced, 256 rows per chunk; cache (key,u,w) in registers
        float kk[16], uu[16], ww[16];
        #pragma unroll
        for (int c = 0; c < 16; ++c) {
            __syncthreads();
            for (int t = tid; t < 256 * 15; t += IB)
                stage[t] = p[c * 256 * 15 + t];
            __syncthreads();
            feat_from_row(stage + tid * 15, feat, kk[c], uu[c], ww[c]);
        }
        __syncthreads();

        // pass 1: histogram + aggregates
        #pragma unroll
        for (int c = 0; c < 16; ++c) {
            int b = min(NB - 1, max(0, (int)((kk[c] - lo) * scale)));
            if (isexp) { atomicAdd(&sA[b], uu[c]); atomicAdd(&sB[b], ww[c]); }
            else       { atomicAdd(&sA[b], 1.0f);  atomicAdd(&sB[b], uu[c]); }
        }
        __syncthreads();

        incl_scan4096(sA, warpTmp);
        __syncthreads();
        incl_scan4096(sB, warpTmp);
        __syncthreads();

        const float TotB = sB[NB - 1];

        // pass 2: O(1) closed form per element (self excluded exactly)
        #pragma unroll
        for (int c = 0; c < 16; ++c) {
            float u = uu[c], w = ww[c];
            int b = min(NB - 1, max(0, (int)((kk[c] - lo) * scale)));
            float res;
            if (isexp) {
                res = w * (sA[b] - u) + u * (TotB - sB[b]);
            } else {
                float cb = sA[b] - 1.0f;
                float ca = (float)N - sA[b];
                res = u * cb - (sB[b] - u) + (TotB - sB[b]) - u * ca;
            }
            g_closed[feat][c * 256 + tid] = res;
        }
        return;
    }

    // ============ PAIRWISE BLOCK: sky_sep + mass_sim, 2-way i-tiling ============
    float*  stage = (float*)(smraw);               // 256 rows x 15 (reused)
    float4* sj    = (float4*)(smraw + 15360);      // [JC]
    const int pb = blockIdx.x - NFEAT;
    const int ib = pb & (NBI - 1);
    const int jb = pb >> 3;                        // NBI = 8
    const int i0 = ib * 512 + tid;
    const int j0 = jb * JC;

    // stage i-rows chunk A (rows ib*512 .. +255), coalesced
    for (int t = tid; t < 256 * 15; t += IB)
        stage[t] = p[ib * 512 * 15 + t];
    __syncthreads();
    float3 a0 = inv_from_row(stage + tid * 15);
    __syncthreads();
    // chunk B (rows +256 .. +511)
    for (int t = tid; t < 256 * 15; t += IB)
        stage[t] = p[(ib * 512 + 256) * 15 + t];
    __syncthreads();
    float3 a1 = inv_from_row(stage + tid * 15);
    __syncthreads();
    // j-rows (64 rows = 960 floats), coalesced
    for (int t = tid; t < JC * 15; t += IB)
        stage[t] = p[j0 * 15 + t];
    __syncthreads();
    if (tid < JC) {
        float3 v = inv_from_row(stage + tid * 15);
        sj[tid] = make_float4(v.x, v.y, v.z, 0.f);
    }
    __syncthreads();

    float sky0 = 0.f, ms0 = 0.f, sky1 = 0.f, ms1 = 0.f;
    #pragma unroll 8
    for (int j = 0; j < JC; ++j) {
        const float4 b = sj[j];
        float dra0 = a0.x - b.x, dde0 = a0.y - b.y;
        float dra1 = a1.x - b.x, dde1 = a1.y - b.y;
        sky0 += f_sqrt(fmaf(dra0, dra0, dde0 * dde0));
        sky1 += f_sqrt(fmaf(dra1, dra1, dde1 * dde1));
        ms0  += f_rcp(1.0f + fabsf(a0.z - b.z));
        ms1  += f_rcp(1.0f + fabsf(a1.z - b.z));
    }
    g_part2[jb][i0]       = make_float2(sky0, ms0);
    g_part2[jb][i0 + 256] = make_float2(sky1, ms1);
}

// ---------------------------------------------------------------------------
// Finish: 8 lanes per row. 128 blocks x 256 threads.
// ---------------------------------------------------------------------------
#define FTB 256
__global__ void __launch_bounds__(FTB) finish_kernel(
    const float* __restrict__ W1, const float* __restrict__ b1,
    const float* __restrict__ ln_g, const float* __restrict__ ln_b,
    const float* __restrict__ W2, const float* __restrict__ b2,
    float* __restrict__ out)
{
    __shared__ float sW1[8 * 32];
    __shared__ float sW2[32 * 16];
    __shared__ float sb1[32], sg[32], sbeta[32], sb2[16];

    for (int k = threadIdx.x; k < 256; k += FTB) sW1[k] = W1[k];
    for (int k = threadIdx.x; k < 512; k += FTB) sW2[k] = W2[k];
    if (threadIdx.x < 32) {
        int k = threadIdx.x;
        sb1[k] = b1[k]; sg[k] = ln_g[k]; sbeta[k] = ln_b[k];
        if (k < 16) sb2[k] = b2[k];
    }
    __syncthreads();

    const int lane = threadIdx.x & 31;
    const int warp = threadIdx.x >> 5;
    const int sub  = lane & 7;
    const int rig  = lane >> 3;
    const int i    = blockIdx.x * 32 + warp * 4 + rig;

    // reduce pairwise partials: lane sums 8 of 64 chunks, butterfly over 8 lanes
    float t_sky = 0.f, t_ms = 0.f;
    #pragma unroll
    for (int cc = 0; cc < 8; ++cc) {
        float2 pp = g_part2[sub * 8 + cc][i];
        t_sky += pp.x; t_ms += pp.y;
    }
    #pragma unroll
    for (int m = 1; m < 8; m <<= 1) {
        t_sky += __shfl_xor_sync(0xFFFFFFFFu, t_sky, m);
        t_ms  += __shfl_xor_sync(0xFFFFFFFFu, t_ms,  m);
    }

    const float inv = 1.0f / (float)(N - 1);
    float x[8];
    x[0] = g_closed[0][i] * inv;
    x[1] = t_sky * inv;
    x[2] = (t_ms - 1.0f) * inv;
    x[3] = g_closed[4][i] * inv;
    x[4] = g_closed[5][i] * inv;
    x[5] = g_closed[1][i] * inv;
    x[6] = g_closed[2][i] * inv;
    x[7] = g_closed[3][i] * inv;

    const int k0 = sub * 4;
    float h[4];
    #pragma unroll
    for (int kk = 0; kk < 4; ++kk) {
        float acc = sb1[k0 + kk];
        #pragma unroll
        for (int f = 0; f < 8; ++f)
            acc = fmaf(x[f], sW1[f * 32 + k0 + kk], acc);
        h[kk] = acc;
    }

    float s1 = h[0] + h[1] + h[2] + h[3];
    #pragma unroll
    for (int m = 1; m < 8; m <<= 1) s1 += __shfl_xor_sync(0xFFFFFFFFu, s1, m);
    float mu = s1 * (1.0f / 32.0f);

    float s2 = 0.f;
    #pragma unroll
    for (int kk = 0; kk < 4; ++kk) {
        float d = h[kk] - mu;
        s2 = fmaf(d, d, s2);
    }
    #pragma unroll
    for (int m = 1; m < 8; m <<= 1) s2 += __shfl_xor_sync(0xFFFFFFFFu, s2, m);
    float rs = rsqrtf(s2 * (1.0f / 32.0f) + 1e-5f);

    #pragma unroll
    for (int kk = 0; kk < 4; ++kk) {
        float v = fmaf((h[kk] - mu) * rs, sg[k0 + kk], sbeta[k0 + kk]);
        h[kk] = 0.5f * v * (1.0f + erff(v * 0.7071067811865475f));
    }

    float o[16];
    #pragma unroll
    for (int oo = 0; oo < 16; ++oo) o[oo] = 0.f;
    #pragma unroll
    for (int kk = 0; kk < 4; ++kk) {
        #pragma unroll
        for (int oo = 0; oo < 16; ++oo)
            o[oo] = fmaf(h[kk], sW2[(k0 + kk) * 16 + oo], o[oo]);
    }
    #pragma unroll
    for (int m = 1; m < 8; m <<= 1) {
        #pragma unroll
        for (int oo = 0; oo < 16; ++oo)
            o[oo] += __shfl_xor_sync(0xFFFFFFFFu, o[oo], m);
    }

    if (sub == 0) {
        float4* op = reinterpret_cast<float4*>(out + i * 16);
        op[0] = make_float4(o[0]  + sb2[0],  o[1]  + sb2[1],
                            o[2]  + sb2[2],  o[3]  + sb2[3]);
        op[1] = make_float4(o[4]  + sb2[4],  o[5]  + sb2[5],
                            o[6]  + sb2[6],  o[7]  + sb2[7]);
        op[2] = make_float4(o[8]  + sb2[8],  o[9]  + sb2[9],
                            o[10] + sb2[10], o[11] + sb2[11]);
        op[3] = make_float4(o[12] + sb2[12], o[13] + sb2[13],
                            o[14] + sb2[14], o[15] + sb2[15]);
    }
}

extern "C" void kernel_launch(void* const* d_in, const int* in_sizes, int n_in,
                              void* d_out, int out_size) {
    const float* params = (const float*)d_in[0];
    const float* W1     = (const float*)d_in[1];
    const float* b1     = (const float*)d_in[2];
    const float* ln_g   = (const float*)d_in[3];
    const float* ln_b   = (const float*)d_in[4];
    const float* W2     = (const float*)d_in[5];
    const float* b2     = (const float*)d_in[6];
    float* out = (float*)d_out;

    fused_kernel<<<NFEAT + NBI * NJ, IB>>>(params);
    finish_kernel<<<N / 32, FTB>>>(W1, b1, ln_g, ln_b, W2, b2, out);
}

// round 13
// speedup vs baseline: 1.1317x; 1.1317x over previous
#include <cuda_runtime.h>

#define N      4096
#define NFEAT  6
#define NB     4096          // fine value-buckets per feature
#define IB     256           // threads per block
#define NBI    8             // i-blocks (512 i each, 2 per thread)
#define NJ     64            // j-chunks
#define JC     64            // j per chunk

// Pairwise partials (sky_sep, mass_sim) per j-chunk
__device__ float2 g_part2[NJ][N];
// Closed-form per-row sums: 0=dt 1=dpsi 2=dra 3=ddec 4=freq_ov 5=dist_ratio
__device__ float  g_closed[NFEAT][N];
// Precomputed per-element data (coalesced layouts)
__device__ float4 g_pi[N];   // {ra, dec, mc30, -}
__device__ float4 g_ab[N];   // {t, psi, ra, dec}       (abs-feature keys)
__device__ float4 g_e4[N];   // {x, 2^x, 2^-x, L}       (freq_ov + dist key)
__device__ float2 g_e5[N];   // {d, 1/d}                (dist_ratio u,w)

__device__ __forceinline__ float f_ex2(float x) {
    float r; asm("ex2.approx.ftz.f32 %0, %1;" : "=f"(r) : "f"(x)); return r;
}
__device__ __forceinline__ float f_lg2(float x) {
    float r; asm("lg2.approx.ftz.f32 %0, %1;" : "=f"(r) : "f"(x)); return r;
}
__device__ __forceinline__ float f_rcp(float x) {
    float r; asm("rcp.approx.ftz.f32 %0, %1;" : "=f"(r) : "f"(x)); return r;
}
__device__ __forceinline__ float f_sqrt(float x) {
    float r; asm("sqrt.approx.ftz.f32 %0, %1;" : "=f"(r) : "f"(x)); return r;
}

// ---------------------------------------------------------------------------
// Kernel A: per-element invariants. 32 blocks x 128 threads; each block
// stages its 128 rows coalesced into smem, then computes from smem rows.
// ---------------------------------------------------------------------------
#define PB 128
__global__ void __launch_bounds__(PB) prep_kernel(const float* __restrict__ p) {
    __shared__ float stage[PB * 15];
    const int tid = threadIdx.x;
    const int base = blockIdx.x * PB;

    for (int t = tid; t < PB * 15; t += PB)
        stage[t] = p[base * 15 + t];
    __syncthreads();

    const float* q = stage + tid * 15;
    float p0 = q[0], p1 = q[1], p2 = q[2];
    float p3 = q[3], p4 = q[4], p5 = q[5], p7 = q[7];

    float m1 = p0 * 95.0f + 5.0f;
    float m2 = p1 * 95.0f + 5.0f;
    float msum = m1 + m2;
    float mc = f_ex2(0.6f * f_lg2(m1 * m2) - 0.2f * f_lg2(msum));
    const float C = 3.1739290899557192f;   // 220*log2(e)/100
    float x = C * f_rcp(msum);
    float d = p2 * 2950.0f + 50.0f;

    const int e = base + tid;
    g_pi[e] = make_float4(p3, p4, mc * (1.0f / 30.0f), 0.f);
    g_ab[e] = make_float4(p5, p7, p3, p4);
    g_e4[e] = make_float4(x, f_ex2(x), f_ex2(-x), f_lg2(d));
    g_e5[e] = make_float2(d, f_rcp(d));
}

// exclusive prefix over 256 thread-values (tid order); all threads call.
__device__ __forceinline__ float excl_scan256(float val, float* warpTmp) {
    const int lane = threadIdx.x & 31, wid = threadIdx.x >> 5;
    float incl = val;
    #pragma unroll
    for (int off = 1; off < 32; off <<= 1) {
        float t = __shfl_up_sync(0xFFFFFFFFu, incl, off);
        if (lane >= off) incl += t;
    }
    __syncthreads();
    if (lane == 31) warpTmp[wid] = incl;
    __syncthreads();
    float base = 0.f;
    #pragma unroll
    for (int ww = 0; ww < 8; ++ww)
        base += (ww < wid) ? warpTmp[ww] : 0.f;
    return base + incl - val;
}

// in-place inclusive scan of arr[NB] with 256 threads (16 per thread)
__device__ __forceinline__ void incl_scan4096(float* arr, float* warpTmp) {
    const int base = threadIdx.x * 16;
    float seg = 0.f;
    #pragma unroll
    for (int q = 0; q < 16; ++q) seg += arr[base + q];
    float run = excl_scan256(seg, warpTmp);
    #pragma unroll
    for (int q = 0; q < 16; ++q) { run += arr[base + q]; arr[base + q] = run; }
}

#define SMEM_SZ (NB * 8 + 64)

// per-feature (key, u, w) from the packed arrays — coalesced vector loads
__device__ __forceinline__ void feat_vals_fast(int e, int feat,
                                               float& key, float& u, float& w) {
    if (feat < 4) {
        float4 ab = g_ab[e];
        key = (feat == 0) ? ab.x : (feat == 1) ? ab.y : (feat == 2) ? ab.z : ab.w;
        u = key; w = 0.f;
    } else if (feat == 4) {
        float4 e4 = g_e4[e];
        key = e4.x; u = e4.y; w = e4.z;
    } else {
        float4 e4 = g_e4[e];
        float2 e5 = g_e5[e];
        key = e4.w; u = e5.x; w = e5.y;
    }
}

// ---------------------------------------------------------------------------
// Kernel B: 6 feature blocks (bucketed closed form) + 512 pairwise blocks.
// ---------------------------------------------------------------------------
__global__ void __launch_bounds__(IB) fused_kernel() {
    __shared__ __align__(16) unsigned char smraw[SMEM_SZ];
    const int tid = threadIdx.x;

    if (blockIdx.x < NFEAT) {
        const int feat = blockIdx.x;
        const bool isexp = (feat >= 4);
        float* sA = (float*)(smraw);             // abs: incl count | exp: incl U
        float* sB = (float*)(smraw + NB * 4);    // abs: incl U     | exp: incl W
        float* warpTmp = (float*)(smraw + NB * 8);

        float lo, scale;
        if      (feat == 4) { lo = 0.01580f; scale = (float)NB / 0.30220f; }
        else if (feat == 5) { lo = 5.64350f; scale = (float)NB / 5.91200f; }
        else                { lo = 0.0f;     scale = (float)NB; }

        for (int q = tid; q < NB; q += IB) { sA[q] = 0.f; sB[q] = 0.f; }
        __syncthreads();

        // pass 1: histogram + aggregates (coalesced reads, spread smem atomics)
        for (int e = tid; e < N; e += IB) {
            float key, u, w; feat_vals_fast(e, feat, key, u, w);
            int b = min(NB - 1, max(0, (int)((key - lo) * scale)));
            if (isexp) { atomicAdd(&sA[b], u); atomicAdd(&sB[b], w); }
            else       { atomicAdd(&sA[b], 1.0f); atomicAdd(&sB[b], u); }
        }
        __syncthreads();

        incl_scan4096(sA, warpTmp);
        __syncthreads();
        incl_scan4096(sB, warpTmp);
        __syncthreads();

        const float TotB = sB[NB - 1];

        // pass 2: O(1) closed form per element (self excluded exactly)
        for (int e = tid; e < N; e += IB) {
            float key, u, w; feat_vals_fast(e, feat, key, u, w);
            int b = min(NB - 1, max(0, (int)((key - lo) * scale)));
            float res;
            if (isexp) {
                res = w * (sA[b] - u) + u * (TotB - sB[b]);
            } else {
                float cb = sA[b] - 1.0f;
                float ca = (float)N - sA[b];
                res = u * cb - (sB[b] - u) + (TotB - sB[b]) - u * ca;
            }
            g_closed[feat][e] = res;
        }
        return;
    }

    // ============ PAIRWISE BLOCK: sky_sep + mass_sim, 2-way i-tiling ============
    float4* sj = (float4*)(smraw);      // [JC] {ra, dec, mc30, pad}
    const int pb = blockIdx.x - NFEAT;
    const int ib = pb & (NBI - 1);
    const int jb = pb >> 3;             // NBI = 8
    const int i0 = ib * 512 + tid;
    const int i1 = i0 + 256;
    const int j0 = jb * JC;

    if (tid < JC) sj[tid] = g_pi[j0 + tid];
    float4 a0 = g_pi[i0];
    float4 a1 = g_pi[i1];
    __syncthreads();

    float sky0 = 0.f, ms0 = 0.f, sky1 = 0.f, ms1 = 0.f;
    #pragma unroll 16
    for (int j = 0; j < JC; ++j) {
        const float4 b = sj[j];
        float dra0 = a0.x - b.x, dde0 = a0.y - b.y;
        float dra1 = a1.x - b.x, dde1 = a1.y - b.y;
        sky0 += f_sqrt(fmaf(dra0, dra0, dde0 * dde0));
        sky1 += f_sqrt(fmaf(dra1, dra1, dde1 * dde1));
        ms0  += f_rcp(1.0f + fabsf(a0.z - b.z));
        ms1  += f_rcp(1.0f + fabsf(a1.z - b.z));
    }
    g_part2[jb][i0] = make_float2(sky0, ms0);
    g_part2[jb][i1] = make_float2(sky1, ms1);
}

// ---------------------------------------------------------------------------
// Finish: 8 lanes per row. 128 blocks x 256 threads.
// ---------------------------------------------------------------------------
#define FTB 256
__global__ void __launch_bounds__(FTB) finish_kernel(
    const float* __restrict__ W1, const float* __restrict__ b1,
    const float* __restrict__ ln_g, const float* __restrict__ ln_b,
    const float* __restrict__ W2, const float* __restrict__ b2,
    float* __restrict__ out)
{
    __shared__ float sW1[8 * 32];
    __shared__ float sW2[32 * 16];
    __shared__ float sb1[32], sg[32], sbeta[32], sb2[16];

    for (int k = threadIdx.x; k < 256; k += FTB) sW1[k] = W1[k];
    for (int k = threadIdx.x; k < 512; k += FTB) sW2[k] = W2[k];
    if (threadIdx.x < 32) {
        int k = threadIdx.x;
        sb1[k] = b1[k]; sg[k] = ln_g[k]; sbeta[k] = ln_b[k];
        if (k < 16) sb2[k] = b2[k];
    }
    __syncthreads();

    const int lane = threadIdx.x & 31;
    const int warp = threadIdx.x >> 5;
    const int sub  = lane & 7;
    const int rig  = lane >> 3;
    const int i    = blockIdx.x * 32 + warp * 4 + rig;

    float t_sky = 0.f, t_ms = 0.f;
    #pragma unroll
    for (int cc = 0; cc < 8; ++cc) {
        float2 pp = g_part2[sub * 8 + cc][i];
        t_sky += pp.x; t_ms += pp.y;
    }
    #pragma unroll
    for (int m = 1; m < 8; m <<= 1) {
        t_sky += __shfl_xor_sync(0xFFFFFFFFu, t_sky, m);
        t_ms  += __shfl_xor_sync(0xFFFFFFFFu, t_ms,  m);
    }

    const float inv = 1.0f / (float)(N - 1);
    float x[8];
    x[0] = g_closed[0][i] * inv;
    x[1] = t_sky * inv;
    x[2] = (t_ms - 1.0f) * inv;
    x[3] = g_closed[4][i] * inv;
    x[4] = g_closed[5][i] * inv;
    x[5] = g_closed[1][i] * inv;
    x[6] = g_closed[2][i] * inv;
    x[7] = g_closed[3][i] * inv;

    const int k0 = sub * 4;
    float h[4];
    #pragma unroll
    for (int kk = 0; kk < 4; ++kk) {
        float acc = sb1[k0 + kk];
        #pragma unroll
        for (int f = 0; f < 8; ++f)
            acc = fmaf(x[f], sW1[f * 32 + k0 + kk], acc);
        h[kk] = acc;
    }

    float s1 = h[0] + h[1] + h[2] + h[3];
    #pragma unroll
    for (int m = 1; m < 8; m <<= 1) s1 += __shfl_xor_sync(0xFFFFFFFFu, s1, m);
    float mu = s1 * (1.0f / 32.0f);

    float s2 = 0.f;
    #pragma unroll
    for (int kk = 0; kk < 4; ++kk) {
        float d = h[kk] - mu;
        s2 = fmaf(d, d, s2);
    }
    #pragma unroll
    for (int m = 1; m < 8; m <<= 1) s2 += __shfl_xor_sync(0xFFFFFFFFu, s2, m);
    float rs = rsqrtf(s2 * (1.0f / 32.0f) + 1e-5f);

    #pragma unroll
    for (int kk = 0; kk < 4; ++kk) {
        float v = fmaf((h[kk] - mu) * rs, sg[k0 + kk], sbeta[k0 + kk]);
        h[kk] = 0.5f * v * (1.0f + erff(v * 0.7071067811865475f));
    }

    float o[16];
    #pragma unroll
    for (int oo = 0; oo < 16; ++oo) o[oo] = 0.f;
    #pragma unroll
    for (int kk = 0; kk < 4; ++kk) {
        #pragma unroll
        for (int oo = 0; oo < 16; ++oo)
            o[oo] = fmaf(h[kk], sW2[(k0 + kk) * 16 + oo], o[oo]);
    }
    #pragma unroll
    for (int m = 1; m < 8; m <<= 1) {
        #pragma unroll
        for (int oo = 0; oo < 16; ++oo)
            o[oo] += __shfl_xor_sync(0xFFFFFFFFu, o[oo], m);
    }

    if (sub == 0) {
        float4* op = reinterpret_cast<float4*>(out + i * 16);
        op[0] = make_float4(o[0]  + sb2[0],  o[1]  + sb2[1],
                            o[2]  + sb2[2],  o[3]  + sb2[3]);
        op[1] = make_float4(o[4]  + sb2[4],  o[5]  + sb2[5],
                            o[6]  + sb2[6],  o[7]  + sb2[7]);
        op[2] = make_float4(o[8]  + sb2[8],  o[9]  + sb2[9],
                            o[10] + sb2[10], o[11] + sb2[11]);
        op[3] = make_float4(o[12] + sb2[12], o[13] + sb2[13],
                            o[14] + sb2[14], o[15] + sb2[15]);
    }
}

extern "C" void kernel_launch(void* const* d_in, const int* in_sizes, int n_in,
                              void* d_out, int out_size) {
    const float* params = (const float*)d_in[0];
    const float* W1     = (const float*)d_in[1];
    const float* b1     = (const float*)d_in[2];
    const float* ln_g   = (const float*)d_in[3];
    const float* ln_b   = (const float*)d_in[4];
    const float* W2     = (const float*)d_in[5];
    const float* b2     = (const float*)d_in[6];
    float* out = (float*)d_out;

    prep_kernel<<<N / PB, PB>>>(params);
    fused_kernel<<<NFEAT + NBI * NJ, IB>>>();
    finish_kernel<<<N / 32, FTB>>>(W1, b1, ln_g, ln_b, W2, b2, out);
}

// round 14
// speedup vs baseline: 1.3131x; 1.1604x over previous
#include <cuda_runtime.h>

#define N      4096
#define NFEAT  6
#define NB     4096          // value-buckets per feature
#define IB     256
#define NBI    8             // pairwise i-blocks (512 i each, 2 per thread)
#define NJ     64            // j-chunks
#define JC     64            // j per chunk
#define NSCAN  12            // scan blocks (6 features x 2 arrays)

// Pairwise partials (sky_sep, mass_sim) per j-chunk
__device__ float2 g_part2[NJ][N];
// Histograms (accumulated by K1 atomics; zeroed by K2 scan blocks after use)
__device__ float g_hA[NFEAT][NB];
__device__ float g_hB[NFEAT][NB];
// Scanned (inclusive) histograms, consumed by K3
__device__ float g_sA[NFEAT][NB];
__device__ float g_sB[NFEAT][NB];
// Precomputed per-element data (coalesced layouts)
__device__ float4 g_pi[N];   // {ra, dec, mc30, -}
__device__ float4 g_ab[N];   // {t, psi, ra, dec}
__device__ float4 g_e4[N];   // {x, 2^x, 2^-x, L}
__device__ float2 g_e5[N];   // {d, 1/d}

__device__ __forceinline__ float f_ex2(float x) {
    float r; asm("ex2.approx.ftz.f32 %0, %1;" : "=f"(r) : "f"(x)); return r;
}
__device__ __forceinline__ float f_lg2(float x) {
    float r; asm("lg2.approx.ftz.f32 %0, %1;" : "=f"(r) : "f"(x)); return r;
}
__device__ __forceinline__ float f_rcp(float x) {
    float r; asm("rcp.approx.ftz.f32 %0, %1;" : "=f"(r) : "f"(x)); return r;
}
__device__ __forceinline__ float f_sqrt(float x) {
    float r; asm("sqrt.approx.ftz.f32 %0, %1;" : "=f"(r) : "f"(x)); return r;
}

#define LO4 0.01580f
#define SC4 ((float)NB / 0.30220f)
#define LO5 5.64350f
#define SC5 ((float)NB / 5.91200f)

__device__ __forceinline__ int bclamp(float key, float lo, float sc) {
    return min(NB - 1, max(0, (int)((key - lo) * sc)));
}

// ---------------------------------------------------------------------------
// K1: invariants + grid-parallel histograms. 16 blocks x 256.
// ---------------------------------------------------------------------------
__global__ void __launch_bounds__(IB) prep_kernel(const float* __restrict__ p) {
    const int e = blockIdx.x * IB + threadIdx.x;
    const float* q = p + e * 15;
    float p0 = q[0], p1 = q[1], p2 = q[2];
    float p3 = q[3], p4 = q[4], p5 = q[5], p7 = q[7];

    float m1 = p0 * 95.0f + 5.0f;
    float m2 = p1 * 95.0f + 5.0f;
    float msum = m1 + m2;
    float mc = f_ex2(0.6f * f_lg2(m1 * m2) - 0.2f * f_lg2(msum));
    const float C = 3.1739290899557192f;   // 220*log2(e)/100
    float x = C * f_rcp(msum);
    float d = p2 * 2950.0f + 50.0f;
    float u4 = f_ex2(x), w4 = f_ex2(-x);
    float L = f_lg2(d), rd = f_rcp(d);

    g_pi[e] = make_float4(p3, p4, mc * (1.0f / 30.0f), 0.f);
    g_ab[e] = make_float4(p5, p7, p3, p4);
    g_e4[e] = make_float4(x, u4, w4, L);
    g_e5[e] = make_float2(d, rd);

    // abs features: hA = count, hB = sum(key)
    float keys[4] = {p5, p7, p3, p4};
    #pragma unroll
    for (int f = 0; f < 4; ++f) {
        int b = bclamp(keys[f], 0.f, (float)NB);
        atomicAdd(&g_hA[f][b], 1.0f);
        atomicAdd(&g_hB[f][b], keys[f]);
    }
    // exp features: hA = sum(u), hB = sum(w)
    int b4 = bclamp(x, LO4, SC4);
    atomicAdd(&g_hA[4][b4], u4);
    atomicAdd(&g_hB[4][b4], w4);
    int b5 = bclamp(L, LO5, SC5);
    atomicAdd(&g_hA[5][b5], d);
    atomicAdd(&g_hB[5][b5], rd);
}

// exclusive prefix over 256 thread-values; all threads call.
__device__ __forceinline__ float excl_scan256(float val, float* warpTmp) {
    const int lane = threadIdx.x & 31, wid = threadIdx.x >> 5;
    float incl = val;
    #pragma unroll
    for (int off = 1; off < 32; off <<= 1) {
        float t = __shfl_up_sync(0xFFFFFFFFu, incl, off);
        if (lane >= off) incl += t;
    }
    __syncthreads();
    if (lane == 31) warpTmp[wid] = incl;
    __syncthreads();
    float base = 0.f;
    #pragma unroll
    for (int ww = 0; ww < 8; ++ww)
        base += (ww < wid) ? warpTmp[ww] : 0.f;
    return base + incl - val;
}

#define SMEM_SZ (NB * 4 + 64)

// ---------------------------------------------------------------------------
// K2: 12 scan blocks + 512 pairwise blocks.
// ---------------------------------------------------------------------------
__global__ void __launch_bounds__(IB) fused_kernel() {
    __shared__ __align__(16) unsigned char smraw[SMEM_SZ];
    const int tid = threadIdx.x;

    if (blockIdx.x < NSCAN) {
        // ---- scan block: inclusive scan of one hist array; re-zero source
        const int f   = blockIdx.x >> 1;
        const int sel = blockIdx.x & 1;
        float* src = sel ? g_hB[f] : g_hA[f];
        float* dst = sel ? g_sB[f] : g_sA[f];
        float* s       = (float*)(smraw);
        float* warpTmp = (float*)(smraw + NB * 4);

        const int base = tid * 16;
        float vals[16];
        float seg = 0.f;
        #pragma unroll
        for (int q = 0; q < 16; ++q) { vals[q] = src[base + q]; seg += vals[q]; }
        float run = excl_scan256(seg, warpTmp);
        #pragma unroll
        for (int q = 0; q < 16; ++q) {
            run += vals[q];
            s[base + q] = run;
        }
        __syncthreads();
        // coalesced write-out + zero the accumulation buffer for next replay
        for (int t = tid; t < NB; t += IB) {
            dst[t] = s[t];
            src[t] = 0.f;
        }
        return;
    }

    // ---- pairwise block: sky_sep + mass_sim, 2-way i-tiling (R10 geometry)
    float4* sj = (float4*)(smraw);      // [JC]
    const int pb = blockIdx.x - NSCAN;
    const int ib = pb & (NBI - 1);
    const int jb = pb >> 3;             // NBI = 8
    const int i0 = ib * 512 + tid;
    const int i1 = i0 + 256;
    const int j0 = jb * JC;

    if (tid < JC) sj[tid] = g_pi[j0 + tid];
    float4 a0 = g_pi[i0];
    float4 a1 = g_pi[i1];
    __syncthreads();

    float sky0 = 0.f, ms0 = 0.f, sky1 = 0.f, ms1 = 0.f;
    #pragma unroll 8
    for (int j = 0; j < JC; ++j) {
        const float4 b = sj[j];
        float dra0 = a0.x - b.x, dde0 = a0.y - b.y;
        float dra1 = a1.x - b.x, dde1 = a1.y - b.y;
        sky0 += f_sqrt(fmaf(dra0, dra0, dde0 * dde0));
        sky1 += f_sqrt(fmaf(dra1, dra1, dde1 * dde1));
        ms0  += f_rcp(1.0f + fabsf(a0.z - b.z));
        ms1  += f_rcp(1.0f + fabsf(a1.z - b.z));
    }
    g_part2[jb][i0] = make_float2(sky0, ms0);
    g_part2[jb][i1] = make_float2(sky1, ms1);
}

// ---------------------------------------------------------------------------
// K3: closed-form eval + reduce + MLP. 8 lanes/row, 128 blocks x 256.
// ---------------------------------------------------------------------------
#define FTB 256
__global__ void __launch_bounds__(FTB) finish_kernel(
    const float* __restrict__ W1, const float* __restrict__ b1,
    const float* __restrict__ ln_g, const float* __restrict__ ln_b,
    const float* __restrict__ W2, const float* __restrict__ b2,
    float* __restrict__ out)
{
    __shared__ float sW1[8 * 32];
    __shared__ float sW2[32 * 16];
    __shared__ float sb1[32], sg[32], sbeta[32], sb2[16];

    for (int k = threadIdx.x; k < 256; k += FTB) sW1[k] = W1[k];
    for (int k = threadIdx.x; k < 512; k += FTB) sW2[k] = W2[k];
    if (threadIdx.x < 32) {
        int k = threadIdx.x;
        sb1[k] = b1[k]; sg[k] = ln_g[k]; sbeta[k] = ln_b[k];
        if (k < 16) sb2[k] = b2[k];
    }
    __syncthreads();

    const int lane = threadIdx.x & 31;
    const int warp = threadIdx.x >> 5;
    const int sub  = lane & 7;
    const int rig  = lane >> 3;
    const int i    = blockIdx.x * 32 + warp * 4 + rig;

    // reduce pairwise partials
    float t_sky = 0.f, t_ms = 0.f;
    #pragma unroll
    for (int cc = 0; cc < 8; ++cc) {
        float2 pp = g_part2[sub * 8 + cc][i];
        t_sky += pp.x; t_ms += pp.y;
    }
    #pragma unroll
    for (int m = 1; m < 8; m <<= 1) {
        t_sky += __shfl_xor_sync(0xFFFFFFFFu, t_sky, m);
        t_ms  += __shfl_xor_sync(0xFFFFFFFFu, t_ms,  m);
    }

    // closed-form features from scanned histograms (O(1) per row)
    float4 ab = g_ab[i];
    float4 e4 = g_e4[i];
    float2 e5 = g_e5[i];

    float cf[6];
    float keys[4] = {ab.x, ab.y, ab.z, ab.w};
    #pragma unroll
    for (int f = 0; f < 4; ++f) {
        float u = keys[f];
        int b = bclamp(u, 0.f, (float)NB);
        float A = g_sA[f][b];            // incl count
        float B = g_sB[f][b];            // incl sum
        float TotB = g_sB[f][NB - 1];
        cf[f] = u * (A - 1.0f) - (B - u) + (TotB - B) - u * ((float)N - A);
    }
    {
        int b = bclamp(e4.x, LO4, SC4);
        float A = g_sA[4][b], B = g_sB[4][b], TotB = g_sB[4][NB - 1];
        cf[4] = e4.z * (A - e4.y) + e4.y * (TotB - B);
    }
    {
        int b = bclamp(e4.w, LO5, SC5);
        float A = g_sA[5][b], B = g_sB[5][b], TotB = g_sB[5][NB - 1];
        cf[5] = e5.y * (A - e5.x) + e5.x * (TotB - B);
    }

    const float inv = 1.0f / (float)(N - 1);
    float x[8];
    x[0] = cf[0] * inv;                  // dt
    x[1] = t_sky * inv;                  // sky_sep (self = 0)
    x[2] = (t_ms - 1.0f) * inv;          // mass_sim (self = 1)
    x[3] = cf[4] * inv;                  // freq_ov (self excluded)
    x[4] = cf[5] * inv;                  // dist_ratio (self excluded)
    x[5] = cf[1] * inv;                  // dpsi
    x[6] = cf[2] * inv;                  // dra
    x[7] = cf[3] * inv;                  // ddec

    const int k0 = sub * 4;
    float h[4];
    #pragma unroll
    for (int kk = 0; kk < 4; ++kk) {
        float acc = sb1[k0 + kk];
        #pragma unroll
        for (int f = 0; f < 8; ++f)
            acc = fmaf(x[f], sW1[f * 32 + k0 + kk], acc);
        h[kk] = acc;
    }

    float s1 = h[0] + h[1] + h[2] + h[3];
    #pragma unroll
    for (int m = 1; m < 8; m <<= 1) s1 += __shfl_xor_sync(0xFFFFFFFFu, s1, m);
    float mu = s1 * (1.0f / 32.0f);

    float s2 = 0.f;
    #pragma unroll
    for (int kk = 0; kk < 4; ++kk) {
        float d = h[kk] - mu;
        s2 = fmaf(d, d, s2);
    }
    #pragma unroll
    for (int m = 1; m < 8; m <<= 1) s2 += __shfl_xor_sync(0xFFFFFFFFu, s2, m);
    float rs = rsqrtf(s2 * (1.0f / 32.0f) + 1e-5f);

    #pragma unroll
    for (int kk = 0; kk < 4; ++kk) {
        float v = fmaf((h[kk] - mu) * rs, sg[k0 + kk], sbeta[k0 + kk]);
        h[kk] = 0.5f * v * (1.0f + erff(v * 0.7071067811865475f));
    }

    float o[16];
    #pragma unroll
    for (int oo = 0; oo < 16; ++oo) o[oo] = 0.f;
    #pragma unroll
    for (int kk = 0; kk < 4; ++kk) {
        #pragma unroll
        for (int oo = 0; oo < 16; ++oo)
            o[oo] = fmaf(h[kk], sW2[(k0 + kk) * 16 + oo], o[oo]);
    }
    #pragma unroll
    for (int m = 1; m < 8; m <<= 1) {
        #pragma unroll
        for (int oo = 0; oo < 16; ++oo)
            o[oo] += __shfl_xor_sync(0xFFFFFFFFu, o[oo], m);
    }

    if (sub == 0) {
        float4* op = reinterpret_cast<float4*>(out + i * 16);
        op[0] = make_float4(o[0]  + sb2[0],  o[1]  + sb2[1],
                            o[2]  + sb2[2],  o[3]  + sb2[3]);
        op[1] = make_float4(o[4]  + sb2[4],  o[5]  + sb2[5],
                            o[6]  + sb2[6],  o[7]  + sb2[7]);
        op[2] = make_float4(o[8]  + sb2[8],  o[9]  + sb2[9],
                            o[10] + sb2[10], o[11] + sb2[11]);
        op[3] = make_float4(o[12] + sb2[12], o[13] + sb2[13],
                            o[14] + sb2[14], o[15] + sb2[15]);
    }
}

extern "C" void kernel_launch(void* const* d_in, const int* in_sizes, int n_in,
                              void* d_out, int out_size) {
    const float* params = (const float*)d_in[0];
    const float* W1     = (const float*)d_in[1];
    const float* b1     = (const float*)d_in[2];
    const float* ln_g   = (const float*)d_in[3];
    const float* ln_b   = (const float*)d_in[4];
    const float* W2     = (const float*)d_in[5];
    const float* b2     = (const float*)d_in[6];
    float* out = (float*)d_out;

    prep_kernel<<<N / IB, IB>>>(params);
    fused_kernel<<<NSCAN + NBI * NJ, IB>>>();
    finish_kernel<<<N / 32, FTB>>>(W1, b1, ln_g, ln_b, W2, b2, out);
}

// round 15
// speedup vs baseline: 1.4325x; 1.0909x over previous
#include <cuda_runtime.h>

#define N      4096
#define NFEAT  6
#define NB     4096          // value-buckets per feature
#define IB     256
#define NBI    8             // pairwise i-blocks (512 i each, 2 per thread)
#define NJ     64            // j-chunks
#define JC     64            // j per chunk
#define NSCAN  12            // scan blocks (6 features x 2 arrays)

// Pairwise partials (sky_sep, mass_sim) per j-chunk
__device__ float2 g_part2[NJ][N];
// Histograms (accumulated by K1 atomics; zeroed by K2 scan blocks after use)
__device__ float g_hA[NFEAT][NB];
__device__ float g_hB[NFEAT][NB];
// Scanned (inclusive) histograms, consumed by K3
__device__ float g_sA[NFEAT][NB];
__device__ float g_sB[NFEAT][NB];
// Precomputed per-element data (coalesced layouts)
__device__ float4 g_pi[N];   // {ra, dec, mc30, -}
__device__ float4 g_ab[N];   // {t, psi, ra, dec}
__device__ float4 g_e4[N];   // {x, 2^x, 2^-x, L}
__device__ float2 g_e5[N];   // {d, 1/d}

__device__ __forceinline__ float f_ex2(float x) {
    float r; asm("ex2.approx.ftz.f32 %0, %1;" : "=f"(r) : "f"(x)); return r;
}
__device__ __forceinline__ float f_lg2(float x) {
    float r; asm("lg2.approx.ftz.f32 %0, %1;" : "=f"(r) : "f"(x)); return r;
}
__device__ __forceinline__ float f_rcp(float x) {
    float r; asm("rcp.approx.ftz.f32 %0, %1;" : "=f"(r) : "f"(x)); return r;
}
__device__ __forceinline__ float f_sqrt(float x) {
    float r; asm("sqrt.approx.ftz.f32 %0, %1;" : "=f"(r) : "f"(x)); return r;
}

#define LO4 0.01580f
#define SC4 ((float)NB / 0.30220f)
#define LO5 5.64350f
#define SC5 ((float)NB / 5.91200f)

__device__ __forceinline__ int bclamp(float key, float lo, float sc) {
    return min(NB - 1, max(0, (int)((key - lo) * sc)));
}

// ---------------------------------------------------------------------------
// K1: invariants + grid-parallel histograms. 128 blocks x 32 threads
// (one warp per SM -> per-warp MLP hides the full DRAM round trip).
// ---------------------------------------------------------------------------
#define PB 32
__global__ void __launch_bounds__(PB) prep_kernel(const float* __restrict__ p) {
    const int e = blockIdx.x * PB + threadIdx.x;
    const float* q = p + e * 15;
    float p0 = q[0], p1 = q[1], p2 = q[2];
    float p3 = q[3], p4 = q[4], p5 = q[5], p7 = q[7];

    float m1 = p0 * 95.0f + 5.0f;
    float m2 = p1 * 95.0f + 5.0f;
    float msum = m1 + m2;
    float mc = f_ex2(0.6f * f_lg2(m1 * m2) - 0.2f * f_lg2(msum));
    const float C = 3.1739290899557192f;   // 220*log2(e)/100
    float x = C * f_rcp(msum);
    float d = p2 * 2950.0f + 50.0f;
    float u4 = f_ex2(x), w4 = f_ex2(-x);
    float L = f_lg2(d), rd = f_rcp(d);

    g_pi[e] = make_float4(p3, p4, mc * (1.0f / 30.0f), 0.f);
    g_ab[e] = make_float4(p5, p7, p3, p4);
    g_e4[e] = make_float4(x, u4, w4, L);
    g_e5[e] = make_float2(d, rd);

    // abs features: hA = count, hB = sum(key)
    float keys[4] = {p5, p7, p3, p4};
    #pragma unroll
    for (int f = 0; f < 4; ++f) {
        int b = bclamp(keys[f], 0.f, (float)NB);
        atomicAdd(&g_hA[f][b], 1.0f);
        atomicAdd(&g_hB[f][b], keys[f]);
    }
    // exp features: hA = sum(u), hB = sum(w)
    int b4 = bclamp(x, LO4, SC4);
    atomicAdd(&g_hA[4][b4], u4);
    atomicAdd(&g_hB[4][b4], w4);
    int b5 = bclamp(L, LO5, SC5);
    atomicAdd(&g_hA[5][b5], d);
    atomicAdd(&g_hB[5][b5], rd);
}

// exclusive prefix over 256 thread-values; all threads call.
__device__ __forceinline__ float excl_scan256(float val, float* warpTmp) {
    const int lane = threadIdx.x & 31, wid = threadIdx.x >> 5;
    float incl = val;
    #pragma unroll
    for (int off = 1; off < 32; off <<= 1) {
        float t = __shfl_up_sync(0xFFFFFFFFu, incl, off);
        if (lane >= off) incl += t;
    }
    __syncthreads();
    if (lane == 31) warpTmp[wid] = incl;
    __syncthreads();
    float base = 0.f;
    #pragma unroll
    for (int ww = 0; ww < 8; ++ww)
        base += (ww < wid) ? warpTmp[ww] : 0.f;
    return base + incl - val;
}

#define SMEM_SZ (NB * 4 + 64)

// ---------------------------------------------------------------------------
// K2: 12 scan blocks + 512 pairwise blocks.
// ---------------------------------------------------------------------------
__global__ void __launch_bounds__(IB) fused_kernel() {
    __shared__ __align__(16) unsigned char smraw[SMEM_SZ];
    const int tid = threadIdx.x;

    if (blockIdx.x < NSCAN) {
        // ---- scan block: inclusive scan of one hist array; re-zero source
        const int f   = blockIdx.x >> 1;
        const int sel = blockIdx.x & 1;
        float* src = sel ? g_hB[f] : g_hA[f];
        float* dst = sel ? g_sB[f] : g_sA[f];
        float* s       = (float*)(smraw);
        float* warpTmp = (float*)(smraw + NB * 4);

        const int base = tid * 16;
        float vals[16];
        float seg = 0.f;
        #pragma unroll
        for (int q = 0; q < 16; ++q) { vals[q] = src[base + q]; seg += vals[q]; }
        float run = excl_scan256(seg, warpTmp);
        #pragma unroll
        for (int q = 0; q < 16; ++q) {
            run += vals[q];
            s[base + q] = run;
        }
        __syncthreads();
        for (int t = tid; t < NB; t += IB) {
            dst[t] = s[t];
            src[t] = 0.f;     // reset accumulation buffer for next replay
        }
        return;
    }

    // ---- pairwise block: sky_sep + mass_sim, 2-way i-tiling
    float4* sj = (float4*)(smraw);      // [JC]
    const int pb = blockIdx.x - NSCAN;
    const int ib = pb & (NBI - 1);
    const int jb = pb >> 3;             // NBI = 8
    const int i0 = ib * 512 + tid;
    const int i1 = i0 + 256;
    const int j0 = jb * JC;

    if (tid < JC) sj[tid] = g_pi[j0 + tid];
    float4 a0 = g_pi[i0];
    float4 a1 = g_pi[i1];
    __syncthreads();

    float sky0 = 0.f, ms0 = 0.f, sky1 = 0.f, ms1 = 0.f;
    #pragma unroll 8
    for (int j = 0; j < JC; ++j) {
        const float4 b = sj[j];
        float dra0 = a0.x - b.x, dde0 = a0.y - b.y;
        float dra1 = a1.x - b.x, dde1 = a1.y - b.y;
        sky0 += f_sqrt(fmaf(dra0, dra0, dde0 * dde0));
        sky1 += f_sqrt(fmaf(dra1, dra1, dde1 * dde1));
        ms0  += f_rcp(fabsf(a0.z - b.z) + 1.0f);
        ms1  += f_rcp(fabsf(a1.z - b.z) + 1.0f);
    }
    g_part2[jb][i0] = make_float2(sky0, ms0);
    g_part2[jb][i1] = make_float2(sky1, ms1);
}

// ---------------------------------------------------------------------------
// K3: closed-form eval + reduce + MLP. 8 lanes/row, 128 blocks x 256.
// ---------------------------------------------------------------------------
#define FTB 256
__global__ void __launch_bounds__(FTB) finish_kernel(
    const float* __restrict__ W1, const float* __restrict__ b1,
    const float* __restrict__ ln_g, const float* __restrict__ ln_b,
    const float* __restrict__ W2, const float* __restrict__ b2,
    float* __restrict__ out)
{
    __shared__ float sW1[8 * 32];
    __shared__ float sW2[32 * 16];
    __shared__ float sb1[32], sg[32], sbeta[32], sb2[16];

    for (int k = threadIdx.x; k < 256; k += FTB) sW1[k] = W1[k];
    for (int k = threadIdx.x; k < 512; k += FTB) sW2[k] = W2[k];
    if (threadIdx.x < 32) {
        int k = threadIdx.x;
        sb1[k] = b1[k]; sg[k] = ln_g[k]; sbeta[k] = ln_b[k];
        if (k < 16) sb2[k] = b2[k];
    }
    __syncthreads();

    const int lane = threadIdx.x & 31;
    const int warp = threadIdx.x >> 5;
    const int sub  = lane & 7;
    const int rig  = lane >> 3;
    const int i    = blockIdx.x * 32 + warp * 4 + rig;

    float t_sky = 0.f, t_ms = 0.f;
    #pragma unroll
    for (int cc = 0; cc < 8; ++cc) {
        float2 pp = g_part2[sub * 8 + cc][i];
        t_sky += pp.x; t_ms += pp.y;
    }
    #pragma unroll
    for (int m = 1; m < 8; m <<= 1) {
        t_sky += __shfl_xor_sync(0xFFFFFFFFu, t_sky, m);
        t_ms  += __shfl_xor_sync(0xFFFFFFFFu, t_ms,  m);
    }

    float4 ab = g_ab[i];
    float4 e4 = g_e4[i];
    float2 e5 = g_e5[i];

    float cf[6];
    float keys[4] = {ab.x, ab.y, ab.z, ab.w};
    #pragma unroll
    for (int f = 0; f < 4; ++f) {
        float u = keys[f];
        int b = bclamp(u, 0.f, (float)NB);
        float A = g_sA[f][b];
        float B = g_sB[f][b];
        float TotB = g_sB[f][NB - 1];
        cf[f] = u * (A - 1.0f) - (B - u) + (TotB - B) - u * ((float)N - A);
    }
    {
        int b = bclamp(e4.x, LO4, SC4);
        float A = g_sA[4][b], B = g_sB[4][b], TotB = g_sB[4][NB - 1];
        cf[4] = e4.z * (A - e4.y) + e4.y * (TotB - B);
    }
    {
        int b = bclamp(e4.w, LO5, SC5);
        float A = g_sA[5][b], B = g_sB[5][b], TotB = g_sB[5][NB - 1];
        cf[5] = e5.y * (A - e5.x) + e5.x * (TotB - B);
    }

    const float inv = 1.0f / (float)(N - 1);
    float x[8];
    x[0] = cf[0] * inv;
    x[1] = t_sky * inv;
    x[2] = (t_ms - 1.0f) * inv;
    x[3] = cf[4] * inv;
    x[4] = cf[5] * inv;
    x[5] = cf[1] * inv;
    x[6] = cf[2] * inv;
    x[7] = cf[3] * inv;

    const int k0 = sub * 4;
    float h[4];
    #pragma unroll
    for (int kk = 0; kk < 4; ++kk) {
        float acc = sb1[k0 + kk];
        #pragma unroll
        for (int f = 0; f < 8; ++f)
            acc = fmaf(x[f], sW1[f * 32 + k0 + kk], acc);
        h[kk] = acc;
    }

    float s1 = h[0] + h[1] + h[2] + h[3];
    #pragma unroll
    for (int m = 1; m < 8; m <<= 1) s1 += __shfl_xor_sync(0xFFFFFFFFu, s1, m);
    float mu = s1 * (1.0f / 32.0f);

    float s2 = 0.f;
    #pragma unroll
    for (int kk = 0; kk < 4; ++kk) {
        float d = h[kk] - mu;
        s2 = fmaf(d, d, s2);
    }
    #pragma unroll
    for (int m = 1; m < 8; m <<= 1) s2 += __shfl_xor_sync(0xFFFFFFFFu, s2, m);
    float rs = rsqrtf(s2 * (1.0f / 32.0f) + 1e-5f);

    #pragma unroll
    for (int kk = 0; kk < 4; ++kk) {
        float v = fmaf((h[kk] - mu) * rs, sg[k0 + kk], sbeta[k0 + kk]);
        h[kk] = 0.5f * v * (1.0f + erff(v * 0.7071067811865475f));
    }

    float o[16];
    #pragma unroll
    for (int oo = 0; oo < 16; ++oo) o[oo] = 0.f;
    #pragma unroll
    for (int kk = 0; kk < 4; ++kk) {
        #pragma unroll
        for (int oo = 0; oo < 16; ++oo)
            o[oo] = fmaf(h[kk], sW2[(k0 + kk) * 16 + oo], o[oo]);
    }
    #pragma unroll
    for (int m = 1; m < 8; m <<= 1) {
        #pragma unroll
        for (int oo = 0; oo < 16; ++oo)
            o[oo] += __shfl_xor_sync(0xFFFFFFFFu, o[oo], m);
    }

    if (sub == 0) {
        float4* op = reinterpret_cast<float4*>(out + i * 16);
        op[0] = make_float4(o[0]  + sb2[0],  o[1]  + sb2[1],
                            o[2]  + sb2[2],  o[3]  + sb2[3]);
        op[1] = make_float4(o[4]  + sb2[4],  o[5]  + sb2[5],
                            o[6]  + sb2[6],  o[7]  + sb2[7]);
        op[2] = make_float4(o[8]  + sb2[8],  o[9]  + sb2[9],
                            o[10] + sb2[10], o[11] + sb2[11]);
        op[3] = make_float4(o[12] + sb2[12], o[13] + sb2[13],
                            o[14] + sb2[14], o[15] + sb2[15]);
    }
}

extern "C" void kernel_launch(void* const* d_in, const int* in_sizes, int n_in,
                              void* d_out, int out_size) {
    const float* params = (const float*)d_in[0];
    const float* W1     = (const float*)d_in[1];
    const float* b1     = (const float*)d_in[2];
    const float* ln_g   = (const float*)d_in[3];
    const float* ln_b   = (const float*)d_in[4];
    const float* W2     = (const float*)d_in[5];
    const float* b2     = (const float*)d_in[6];
    float* out = (float*)d_out;

    prep_kernel<<<N / PB, PB>>>(params);
    fused_kernel<<<NSCAN + NBI * NJ, IB>>>();
    finish_kernel<<<N / 32, FTB>>>(W1, b1, ln_g, ln_b, W2, b2, out);
}

// round 16
// speedup vs baseline: 1.5639x; 1.0917x over previous
#include <cuda_runtime.h>

#define N      4096
#define NFEAT  6
#define NB     4096
#define IB     256
#define NPREP  16            // prep blocks
#define NSCAN  12            // scan blocks
#define NBI    8             // pairwise i-blocks (512 i each, 2 per thread)
#define NJ     64
#define JC     64

// Pairwise partials (sky_sep, mass_sim) per j-chunk
__device__ float2 g_part2[NJ][N];
// Histograms (filled by prep blocks; zeroed by scan blocks after use)
__device__ float g_hA[NFEAT][NB];
__device__ float g_hB[NFEAT][NB];
// Scanned (inclusive) histograms, consumed by finish
__device__ float g_sA[NFEAT][NB];
__device__ float g_sB[NFEAT][NB];
// Per-element packed data for finish's closed-form eval
__device__ float4 g_ab[N];   // {t, psi, ra, dec}
__device__ float4 g_e4[N];   // {x, 2^x, 2^-x, L}
__device__ float2 g_e5[N];   // {d, 1/d}
// prep completion counter (reset by finish kernel each replay)
__device__ int g_done;

__device__ __forceinline__ float f_ex2(float x) {
    float r; asm("ex2.approx.ftz.f32 %0, %1;" : "=f"(r) : "f"(x)); return r;
}
__device__ __forceinline__ float f_lg2(float x) {
    float r; asm("lg2.approx.ftz.f32 %0, %1;" : "=f"(r) : "f"(x)); return r;
}
__device__ __forceinline__ float f_rcp(float x) {
    float r; asm("rcp.approx.ftz.f32 %0, %1;" : "=f"(r) : "f"(x)); return r;
}
__device__ __forceinline__ float f_sqrt(float x) {
    float r; asm("sqrt.approx.ftz.f32 %0, %1;" : "=f"(r) : "f"(x)); return r;
}

#define LO4 0.01580f
#define SC4 ((float)NB / 0.30220f)
#define LO5 5.64350f
#define SC5 ((float)NB / 5.91200f)

__device__ __forceinline__ int bclamp(float key, float lo, float sc) {
    return min(NB - 1, max(0, (int)((key - lo) * sc)));
}

// (ra, dec, mc30) straight from p (scattered loads; hidden at high occupancy)
__device__ __forceinline__ float3 pair_inv(const float* __restrict__ p, int idx) {
    const float* q = p + idx * 15;
    float m1 = q[0] * 95.0f + 5.0f;
    float m2 = q[1] * 95.0f + 5.0f;
    float mc = f_ex2(0.6f * f_lg2(m1 * m2) - 0.2f * f_lg2(m1 + m2));
    return make_float3(q[3], q[4], mc * (1.0f / 30.0f));
}

// exclusive prefix over 256 thread-values; all threads call.
__device__ __forceinline__ float excl_scan256(float val, float* warpTmp) {
    const int lane = threadIdx.x & 31, wid = threadIdx.x >> 5;
    float incl = val;
    #pragma unroll
    for (int off = 1; off < 32; off <<= 1) {
        float t = __shfl_up_sync(0xFFFFFFFFu, incl, off);
        if (lane >= off) incl += t;
    }
    __syncthreads();
    if (lane == 31) warpTmp[wid] = incl;
    __syncthreads();
    float base = 0.f;
    #pragma unroll
    for (int ww = 0; ww < 8; ++ww)
        base += (ww < wid) ? warpTmp[ww] : 0.f;
    return base + incl - val;
}

#define SMEM_SZ (NB * 4 + 64)

// ---------------------------------------------------------------------------
// K_fused: 16 prep + 12 scan (spin-wait) + 512 pairwise = 540 blocks.
// All blocks are co-resident (540 < 148 SMs x 8 blocks) => spin is safe.
// ---------------------------------------------------------------------------
__global__ void __launch_bounds__(IB) fused_kernel(const float* __restrict__ p) {
    __shared__ __align__(16) unsigned char smraw[SMEM_SZ];
    const int tid = threadIdx.x;

    if (blockIdx.x < NPREP) {
        // ============ PREP BLOCK: invariants + grid-parallel histograms ============
        const int e = blockIdx.x * IB + tid;
        const float* q = p + e * 15;
        float p0 = q[0], p1 = q[1], p2 = q[2];
        float p3 = q[3], p4 = q[4], p5 = q[5], p7 = q[7];

        float m1 = p0 * 95.0f + 5.0f;
        float m2 = p1 * 95.0f + 5.0f;
        float msum = m1 + m2;
        float mc = f_ex2(0.6f * f_lg2(m1 * m2) - 0.2f * f_lg2(msum));
        const float C = 3.1739290899557192f;   // 220*log2(e)/100
        float x = C * f_rcp(msum);
        float d = p2 * 2950.0f + 50.0f;
        float u4 = f_ex2(x), w4 = f_ex2(-x);
        float L = f_lg2(d), rd = f_rcp(d);

        g_ab[e] = make_float4(p5, p7, p3, p4);
        g_e4[e] = make_float4(x, u4, w4, L);
        g_e5[e] = make_float2(d, rd);
        (void)mc;

        float keys[4] = {p5, p7, p3, p4};
        #pragma unroll
        for (int f = 0; f < 4; ++f) {
            int b = bclamp(keys[f], 0.f, (float)NB);
            atomicAdd(&g_hA[f][b], 1.0f);
            atomicAdd(&g_hB[f][b], keys[f]);
        }
        int b4 = bclamp(x, LO4, SC4);
        atomicAdd(&g_hA[4][b4], u4);
        atomicAdd(&g_hB[4][b4], w4);
        int b5 = bclamp(L, LO5, SC5);
        atomicAdd(&g_hA[5][b5], d);
        atomicAdd(&g_hB[5][b5], rd);

        __threadfence();
        __syncthreads();
        if (tid == 0) atomicAdd(&g_done, 1);
        return;
    }

    if (blockIdx.x < NPREP + NSCAN) {
        // ============ SCAN BLOCK: wait for prep, then scan + re-zero ============
        if (tid == 0) {
            while (atomicAdd(&g_done, 0) < NPREP) { /* spin; prep co-resident */ }
        }
        __syncthreads();
        __threadfence();   // acquire

        const int sb  = blockIdx.x - NPREP;
        const int f   = sb >> 1;
        const int sel = sb & 1;
        float* src = sel ? g_hB[f] : g_hA[f];
        float* dst = sel ? g_sB[f] : g_sA[f];
        float* s       = (float*)(smraw);
        float* warpTmp = (float*)(smraw + NB * 4);

        const int base = tid * 16;
        float vals[16];
        float seg = 0.f;
        #pragma unroll
        for (int q2 = 0; q2 < 16; ++q2) { vals[q2] = src[base + q2]; seg += vals[q2]; }
        float run = excl_scan256(seg, warpTmp);
        #pragma unroll
        for (int q2 = 0; q2 < 16; ++q2) {
            run += vals[q2];
            s[base + q2] = run;
        }
        __syncthreads();
        for (int t = tid; t < NB; t += IB) {
            dst[t] = s[t];
            src[t] = 0.f;     // reset accumulation buffer for next replay
        }
        return;
    }

    // ============ PAIRWISE BLOCK: sky_sep + mass_sim, 2-way i-tiling ============
    float4* sj = (float4*)(smraw);      // [JC]
    const int pb = blockIdx.x - NPREP - NSCAN;
    const int ib = pb & (NBI - 1);
    const int jb = pb >> 3;             // NBI = 8
    const int i0 = ib * 512 + tid;
    const int i1 = i0 + 256;
    const int j0 = jb * JC;

    if (tid < JC) {
        float3 v = pair_inv(p, j0 + tid);
        sj[tid] = make_float4(v.x, v.y, v.z, 0.f);
    }
    float3 a0 = pair_inv(p, i0);
    float3 a1 = pair_inv(p, i1);
    __syncthreads();

    float sky0 = 0.f, ms0 = 0.f, sky1 = 0.f, ms1 = 0.f;
    #pragma unroll 8
    for (int j = 0; j < JC; ++j) {
        const float4 b = sj[j];
        float dra0 = a0.x - b.x, dde0 = a0.y - b.y;
        float dra1 = a1.x - b.x, dde1 = a1.y - b.y;
        sky0 += f_sqrt(fmaf(dra0, dra0, dde0 * dde0));
        sky1 += f_sqrt(fmaf(dra1, dra1, dde1 * dde1));
        ms0  += f_rcp(fabsf(a0.z - b.z) + 1.0f);
        ms1  += f_rcp(fabsf(a1.z - b.z) + 1.0f);
    }
    g_part2[jb][i0] = make_float2(sky0, ms0);
    g_part2[jb][i1] = make_float2(sky1, ms1);
}

// ---------------------------------------------------------------------------
// K_finish: closed-form eval + reduce + MLP. 8 lanes/row, 128 blocks x 256.
// ---------------------------------------------------------------------------
#define FTB 256
__global__ void __launch_bounds__(FTB) finish_kernel(
    const float* __restrict__ W1, const float* __restrict__ b1,
    const float* __restrict__ ln_g, const float* __restrict__ ln_b,
    const float* __restrict__ W2, const float* __restrict__ b2,
    float* __restrict__ out)
{
    __shared__ float sW1[8 * 32];
    __shared__ float sW2[32 * 16];
    __shared__ float sb1[32], sg[32], sbeta[32], sb2[16];

    if (blockIdx.x == 0 && threadIdx.x == 0) g_done = 0;   // reset for next replay

    for (int k = threadIdx.x; k < 256; k += FTB) sW1[k] = W1[k];
    for (int k = threadIdx.x; k < 512; k += FTB) sW2[k] = W2[k];
    if (threadIdx.x < 32) {
        int k = threadIdx.x;
        sb1[k] = b1[k]; sg[k] = ln_g[k]; sbeta[k] = ln_b[k];
        if (k < 16) sb2[k] = b2[k];
    }
    __syncthreads();

    const int lane = threadIdx.x & 31;
    const int warp = threadIdx.x >> 5;
    const int sub  = lane & 7;
    const int rig  = lane >> 3;
    const int i    = blockIdx.x * 32 + warp * 4 + rig;

    float t_sky = 0.f, t_ms = 0.f;
    #pragma unroll
    for (int cc = 0; cc < 8; ++cc) {
        float2 pp = g_part2[sub * 8 + cc][i];
        t_sky += pp.x; t_ms += pp.y;
    }
    #pragma unroll
    for (int m = 1; m < 8; m <<= 1) {
        t_sky += __shfl_xor_sync(0xFFFFFFFFu, t_sky, m);
        t_ms  += __shfl_xor_sync(0xFFFFFFFFu, t_ms,  m);
    }

    float4 ab = g_ab[i];
    float4 e4 = g_e4[i];
    float2 e5 = g_e5[i];

    float cf[6];
    float keys[4] = {ab.x, ab.y, ab.z, ab.w};
    #pragma unroll
    for (int f = 0; f < 4; ++f) {
        float u = keys[f];
        int b = bclamp(u, 0.f, (float)NB);
        float A = g_sA[f][b];
        float B = g_sB[f][b];
        float TotB = g_sB[f][NB - 1];
        cf[f] = u * (A - 1.0f) - (B - u) + (TotB - B) - u * ((float)N - A);
    }
    {
        int b = bclamp(e4.x, LO4, SC4);
        float A = g_sA[4][b], B = g_sB[4][b], TotB = g_sB[4][NB - 1];
        cf[4] = e4.z * (A - e4.y) + e4.y * (TotB - B);
    }
    {
        int b = bclamp(e4.w, LO5, SC5);
        float A = g_sA[5][b], B = g_sB[5][b], TotB = g_sB[5][NB - 1];
        cf[5] = e5.y * (A - e5.x) + e5.x * (TotB - B);
    }

    const float inv = 1.0f / (float)(N - 1);
    float x[8];
    x[0] = cf[0] * inv;
    x[1] = t_sky * inv;
    x[2] = (t_ms - 1.0f) * inv;
    x[3] = cf[4] * inv;
    x[4] = cf[5] * inv;
    x[5] = cf[1] * inv;
    x[6] = cf[2] * inv;
    x[7] = cf[3] * inv;

    const int k0 = sub * 4;
    float h[4];
    #pragma unroll
    for (int kk = 0; kk < 4; ++kk) {
        float acc = sb1[k0 + kk];
        #pragma unroll
        for (int f = 0; f < 8; ++f)
            acc = fmaf(x[f], sW1[f * 32 + k0 + kk], acc);
        h[kk] = acc;
    }

    float s1 = h[0] + h[1] + h[2] + h[3];
    #pragma unroll
    for (int m = 1; m < 8; m <<= 1) s1 += __shfl_xor_sync(0xFFFFFFFFu, s1, m);
    float mu = s1 * (1.0f / 32.0f);

    float s2 = 0.f;
    #pragma unroll
    for (int kk = 0; kk < 4; ++kk) {
        float d = h[kk] - mu;
        s2 = fmaf(d, d, s2);
    }
    #pragma unroll
    for (int m = 1; m < 8; m <<= 1) s2 += __shfl_xor_sync(0xFFFFFFFFu, s2, m);
    float rs = rsqrtf(s2 * (1.0f / 32.0f) + 1e-5f);

    #pragma unroll
    for (int kk = 0; kk < 4; ++kk) {
        float v = fmaf((h[kk] - mu) * rs, sg[k0 + kk], sbeta[k0 + kk]);
        h[kk] = 0.5f * v * (1.0f + erff(v * 0.7071067811865475f));
    }

    float o[16];
    #pragma unroll
    for (int oo = 0; oo < 16; ++oo) o[oo] = 0.f;
    #pragma unroll
    for (int kk = 0; kk < 4; ++kk) {
        #pragma unroll
        for (int oo = 0; oo < 16; ++oo)
            o[oo] = fmaf(h[kk], sW2[(k0 + kk) * 16 + oo], o[oo]);
    }
    #pragma unroll
    for (int m = 1; m < 8; m <<= 1) {
        #pragma unroll
        for (int oo = 0; oo < 16; ++oo)
            o[oo] += __shfl_xor_sync(0xFFFFFFFFu, o[oo], m);
    }

    if (sub == 0) {
        float4* op = reinterpret_cast<float4*>(out + i * 16);
        op[0] = make_float4(o[0]  + sb2[0],  o[1]  + sb2[1],
                            o[2]  + sb2[2],  o[3]  + sb2[3]);
        op[1] = make_float4(o[4]  + sb2[4],  o[5]  + sb2[5],
                            o[6]  + sb2[6],  o[7]  + sb2[7]);
        op[2] = make_float4(o[8]  + sb2[8],  o[9]  + sb2[9],
                            o[10] + sb2[10], o[11] + sb2[11]);
        op[3] = make_float4(o[12] + sb2[12], o[13] + sb2[13],
                            o[14] + sb2[14], o[15] + sb2[15]);
    }
}

extern "C" void kernel_launch(void* const* d_in, const int* in_sizes, int n_in,
                              void* d_out, int out_size) {
    const float* params = (const float*)d_in[0];
    const float* W1     = (const float*)d_in[1];
    const float* b1     = (const float*)d_in[2];
    const float* ln_g   = (const float*)d_in[3];
    const float* ln_b   = (const float*)d_in[4];
    const float* W2     = (const float*)d_in[5];
    const float* b2     = (const float*)d_in[6];
    float* out = (float*)d_out;

    fused_kernel<<<NPREP + NSCAN + NBI * NJ, IB>>>(params);
    finish_kernel<<<N / 32, FTB>>>(W1, b1, ln_g, ln_b, W2, b2, out);
}

// round 17
// speedup vs baseline: 1.5878x; 1.0153x over previous
#include <cuda_runtime.h>

#define N      4096
#define NFEAT  6
#define NB     4096
#define IB     256
#define NPREP  16            // prep blocks
#define NSCAN  12            // scan blocks
#define NBI    8             // pairwise i-blocks (512 i each, 2 per thread)
#define NJ     64
#define JC     64
#define NPAIR  (NBI * NJ)    // 512
#define NFIN   128           // finisher blocks (first 128 pairwise blocks)
#define ALL_TGT (NPAIR + NSCAN)   // 524

// Pairwise partials (sky_sep, mass_sim) per j-chunk
__device__ float2 g_part2[NJ][N];
// Histograms (filled by prep blocks; zeroed by scan blocks after use)
__device__ float g_hA[NFEAT][NB];
__device__ float g_hB[NFEAT][NB];
// Scanned (inclusive) histograms
__device__ float g_sA[NFEAT][NB];
__device__ float g_sB[NFEAT][NB];
// Per-element packed data for the closed-form eval
__device__ float4 g_ab[N];   // {t, psi, ra, dec}
__device__ float4 g_e4[N];   // {x, 2^x, 2^-x, L}
__device__ float2 g_e5[N];   // {d, 1/d}
// progress counters (reset by last finisher each replay)
__device__ int g_done;       // prep blocks completed
__device__ int g_all;        // pairwise + scan blocks completed
__device__ int g_fobs;       // finishers past the barrier

__device__ __forceinline__ float f_ex2(float x) {
    float r; asm("ex2.approx.ftz.f32 %0, %1;" : "=f"(r) : "f"(x)); return r;
}
__device__ __forceinline__ float f_lg2(float x) {
    float r; asm("lg2.approx.ftz.f32 %0, %1;" : "=f"(r) : "f"(x)); return r;
}
__device__ __forceinline__ float f_rcp(float x) {
    float r; asm("rcp.approx.ftz.f32 %0, %1;" : "=f"(r) : "f"(x)); return r;
}
__device__ __forceinline__ float f_sqrt(float x) {
    float r; asm("sqrt.approx.ftz.f32 %0, %1;" : "=f"(r) : "f"(x)); return r;
}

#define LO4 0.01580f
#define SC4 ((float)NB / 0.30220f)
#define LO5 5.64350f
#define SC5 ((float)NB / 5.91200f)

__device__ __forceinline__ int bclamp(float key, float lo, float sc) {
    return min(NB - 1, max(0, (int)((key - lo) * sc)));
}

__device__ __forceinline__ float3 pair_inv(const float* __restrict__ p, int idx) {
    const float* q = p + idx * 15;
    float m1 = q[0] * 95.0f + 5.0f;
    float m2 = q[1] * 95.0f + 5.0f;
    float mc = f_ex2(0.6f * f_lg2(m1 * m2) - 0.2f * f_lg2(m1 + m2));
    return make_float3(q[3], q[4], mc * (1.0f / 30.0f));
}

__device__ __forceinline__ float excl_scan256(float val, float* warpTmp) {
    const int lane = threadIdx.x & 31, wid = threadIdx.x >> 5;
    float incl = val;
    #pragma unroll
    for (int off = 1; off < 32; off <<= 1) {
        float t = __shfl_up_sync(0xFFFFFFFFu, incl, off);
        if (lane >= off) incl += t;
    }
    __syncthreads();
    if (lane == 31) warpTmp[wid] = incl;
    __syncthreads();
    float base = 0.f;
    #pragma unroll
    for (int ww = 0; ww < 8; ++ww)
        base += (ww < wid) ? warpTmp[ww] : 0.f;
    return base + incl - val;
}

#define SMEM_SZ (NB * 4 + 64)

// ---------------------------------------------------------------------------
// Single kernel: 16 prep + 12 scan + 512 pairwise (first 128 also finish).
// __launch_bounds__(256,4): 4 blocks/SM guaranteed -> 592 >= 540 co-resident,
// so all grid-wide spin-waits are deadlock-free.
// ---------------------------------------------------------------------------
__global__ void __launch_bounds__(IB, 4) fused_kernel(
    const float* __restrict__ p,
    const float* __restrict__ W1, const float* __restrict__ b1,
    const float* __restrict__ ln_g, const float* __restrict__ ln_b,
    const float* __restrict__ W2, const float* __restrict__ b2,
    float* __restrict__ out)
{
    __shared__ __align__(16) unsigned char smraw[SMEM_SZ];
    const int tid = threadIdx.x;

    if (blockIdx.x < NPREP) {
        // ============ PREP: invariants + grid-parallel histograms ============
        const int e = blockIdx.x * IB + tid;
        const float* q = p + e * 15;
        float p0 = q[0], p1 = q[1], p2 = q[2];
        float p3 = q[3], p4 = q[4], p5 = q[5], p7 = q[7];

        float m1 = p0 * 95.0f + 5.0f;
        float m2 = p1 * 95.0f + 5.0f;
        float msum = m1 + m2;
        const float C = 3.1739290899557192f;   // 220*log2(e)/100
        float x = C * f_rcp(msum);
        float d = p2 * 2950.0f + 50.0f;
        float u4 = f_ex2(x), w4 = f_ex2(-x);
        float L = f_lg2(d), rd = f_rcp(d);

        g_ab[e] = make_float4(p5, p7, p3, p4);
        g_e4[e] = make_float4(x, u4, w4, L);
        g_e5[e] = make_float2(d, rd);

        float keys[4] = {p5, p7, p3, p4};
        #pragma unroll
        for (int f = 0; f < 4; ++f) {
            int b = bclamp(keys[f], 0.f, (float)NB);
            atomicAdd(&g_hA[f][b], 1.0f);
            atomicAdd(&g_hB[f][b], keys[f]);
        }
        int b4 = bclamp(x, LO4, SC4);
        atomicAdd(&g_hA[4][b4], u4);
        atomicAdd(&g_hB[4][b4], w4);
        int b5 = bclamp(L, LO5, SC5);
        atomicAdd(&g_hA[5][b5], d);
        atomicAdd(&g_hB[5][b5], rd);

        __threadfence();
        __syncthreads();
        if (tid == 0) atomicAdd(&g_done, 1);
        return;
    }

    if (blockIdx.x < NPREP + NSCAN) {
        // ============ SCAN: wait for prep, scan one hist, re-zero it ============
        if (tid == 0) {
            while (atomicAdd(&g_done, 0) < NPREP) {}
        }
        __syncthreads();
        __threadfence();

        const int sb  = blockIdx.x - NPREP;
        const int f   = sb >> 1;
        const int sel = sb & 1;
        float* src = sel ? g_hB[f] : g_hA[f];
        float* dst = sel ? g_sB[f] : g_sA[f];
        float* s       = (float*)(smraw);
        float* warpTmp = (float*)(smraw + NB * 4);

        const int base = tid * 16;
        float vals[16];
        float seg = 0.f;
        #pragma unroll
        for (int q2 = 0; q2 < 16; ++q2) { vals[q2] = src[base + q2]; seg += vals[q2]; }
        float run = excl_scan256(seg, warpTmp);
        #pragma unroll
        for (int q2 = 0; q2 < 16; ++q2) { run += vals[q2]; s[base + q2] = run; }
        __syncthreads();
        for (int t = tid; t < NB; t += IB) {
            dst[t] = s[t];
            src[t] = 0.f;
        }
        __threadfence();
        __syncthreads();
        if (tid == 0) atomicAdd(&g_all, 1);
        return;
    }

    // ============ PAIRWISE: sky_sep + mass_sim, 2-way i-tiling ============
    float4* sj = (float4*)(smraw);
    const int pb = blockIdx.x - NPREP - NSCAN;
    const int ib = pb & (NBI - 1);
    const int jb = pb >> 3;
    const int i0 = ib * 512 + tid;
    const int i1 = i0 + 256;
    const int j0 = jb * JC;

    if (tid < JC) {
        float3 v = pair_inv(p, j0 + tid);
        sj[tid] = make_float4(v.x, v.y, v.z, 0.f);
    }
    float3 a0 = pair_inv(p, i0);
    float3 a1 = pair_inv(p, i1);
    __syncthreads();

    float sky0 = 0.f, ms0 = 0.f, sky1 = 0.f, ms1 = 0.f;
    #pragma unroll 8
    for (int j = 0; j < JC; ++j) {
        const float4 b = sj[j];
        float dra0 = a0.x - b.x, dde0 = a0.y - b.y;
        float dra1 = a1.x - b.x, dde1 = a1.y - b.y;
        sky0 += f_sqrt(fmaf(dra0, dra0, dde0 * dde0));
        sky1 += f_sqrt(fmaf(dra1, dra1, dde1 * dde1));
        ms0  += f_rcp(fabsf(a0.z - b.z) + 1.0f);
        ms1  += f_rcp(fabsf(a1.z - b.z) + 1.0f);
    }
    g_part2[jb][i0] = make_float2(sky0, ms0);
    g_part2[jb][i1] = make_float2(sky1, ms1);

    __threadfence();
    __syncthreads();
    if (tid == 0) atomicAdd(&g_all, 1);

    if (pb >= NFIN) return;

    // ============ FINISH (first 128 pairwise blocks): wait, then MLP ============
    if (tid == 0) {
        while (atomicAdd(&g_all, 0) < ALL_TGT) {}
    }
    __syncthreads();
    __threadfence();

    // reuse smem for weights
    float* sw = (float*)(smraw);
    float* sW1   = sw;          // [256]
    float* sW2   = sw + 256;    // [512]
    float* sb1   = sw + 768;    // [32]
    float* sg    = sw + 800;    // [32]
    float* sbeta = sw + 832;    // [32]
    float* sb2   = sw + 864;    // [16]
    for (int k = tid; k < 256; k += IB) sW1[k] = W1[k];
    for (int k = tid; k < 512; k += IB) sW2[k] = W2[k];
    if (tid < 32) {
        sb1[tid] = b1[tid]; sg[tid] = ln_g[tid]; sbeta[tid] = ln_b[tid];
        if (tid < 16) sb2[tid] = b2[tid];
    }
    __syncthreads();

    const int lane = tid & 31;
    const int warp = tid >> 5;
    const int sub  = lane & 7;
    const int rig  = lane >> 3;
    const int i    = pb * 32 + warp * 4 + rig;

    float t_sky = 0.f, t_ms = 0.f;
    #pragma unroll
    for (int cc = 0; cc < 8; ++cc) {
        float2 pp = g_part2[sub * 8 + cc][i];
        t_sky += pp.x; t_ms += pp.y;
    }
    #pragma unroll
    for (int m = 1; m < 8; m <<= 1) {
        t_sky += __shfl_xor_sync(0xFFFFFFFFu, t_sky, m);
        t_ms  += __shfl_xor_sync(0xFFFFFFFFu, t_ms,  m);
    }

    float4 ab = g_ab[i];
    float4 e4 = g_e4[i];
    float2 e5 = g_e5[i];

    float cf[6];
    float keys[4] = {ab.x, ab.y, ab.z, ab.w};
    #pragma unroll
    for (int f = 0; f < 4; ++f) {
        float u = keys[f];
        int b = bclamp(u, 0.f, (float)NB);
        float A = g_sA[f][b];
        float B = g_sB[f][b];
        float TotB = g_sB[f][NB - 1];
        cf[f] = u * (A - 1.0f) - (B - u) + (TotB - B) - u * ((float)N - A);
    }
    {
        int b = bclamp(e4.x, LO4, SC4);
        float A = g_sA[4][b], B = g_sB[4][b], TotB = g_sB[4][NB - 1];
        cf[4] = e4.z * (A - e4.y) + e4.y * (TotB - B);
    }
    {
        int b = bclamp(e4.w, LO5, SC5);
        float A = g_sA[5][b], B = g_sB[5][b], TotB = g_sB[5][NB - 1];
        cf[5] = e5.y * (A - e5.x) + e5.x * (TotB - B);
    }

    const float inv = 1.0f / (float)(N - 1);
    float x2[8];
    x2[0] = cf[0] * inv;
    x2[1] = t_sky * inv;
    x2[2] = (t_ms - 1.0f) * inv;
    x2[3] = cf[4] * inv;
    x2[4] = cf[5] * inv;
    x2[5] = cf[1] * inv;
    x2[6] = cf[2] * inv;
    x2[7] = cf[3] * inv;

    const int k0 = sub * 4;
    float h[4];
    #pragma unroll
    for (int kk = 0; kk < 4; ++kk) {
        float acc = sb1[k0 + kk];
        #pragma unroll
        for (int f = 0; f < 8; ++f)
            acc = fmaf(x2[f], sW1[f * 32 + k0 + kk], acc);
        h[kk] = acc;
    }

    float s1 = h[0] + h[1] + h[2] + h[3];
    #pragma unroll
    for (int m = 1; m < 8; m <<= 1) s1 += __shfl_xor_sync(0xFFFFFFFFu, s1, m);
    float mu = s1 * (1.0f / 32.0f);

    float s2 = 0.f;
    #pragma unroll
    for (int kk = 0; kk < 4; ++kk) {
        float dd = h[kk] - mu;
        s2 = fmaf(dd, dd, s2);
    }
    #pragma unroll
    for (int m = 1; m < 8; m <<= 1) s2 += __shfl_xor_sync(0xFFFFFFFFu, s2, m);
    float rs = rsqrtf(s2 * (1.0f / 32.0f) + 1e-5f);

    #pragma unroll
    for (int kk = 0; kk < 4; ++kk) {
        float v = fmaf((h[kk] - mu) * rs, sg[k0 + kk], sbeta[k0 + kk]);
        h[kk] = 0.5f * v * (1.0f + erff(v * 0.7071067811865475f));
    }

    float o[16];
    #pragma unroll
    for (int oo = 0; oo < 16; ++oo) o[oo] = 0.f;
    #pragma unroll
    for (int kk = 0; kk < 4; ++kk) {
        #pragma unroll
        for (int oo = 0; oo < 16; ++oo)
            o[oo] = fmaf(h[kk], sW2[(k0 + kk) * 16 + oo], o[oo]);
    }
    #pragma unroll
    for (int m = 1; m < 8; m <<= 1) {
        #pragma unroll
        for (int oo = 0; oo < 16; ++oo)
            o[oo] += __shfl_xor_sync(0xFFFFFFFFu, o[oo], m);
    }

    if (sub == 0) {
        float4* op = reinterpret_cast<float4*>(out + i * 16);
        op[0] = make_float4(o[0]  + sb2[0],  o[1]  + sb2[1],
                            o[2]  + sb2[2],  o[3]  + sb2[3]);
        op[1] = make_float4(o[4]  + sb2[4],  o[5]  + sb2[5],
                            o[6]  + sb2[6],  o[7]  + sb2[7]);
        op[2] = make_float4(o[8]  + sb2[8],  o[9]  + sb2[9],
                            o[10] + sb2[10], o[11] + sb2[11]);
        op[3] = make_float4(o[12] + sb2[12], o[13] + sb2[13],
                            o[14] + sb2[14], o[15] + sb2[15]);
    }

    // last finisher resets counters for the next graph replay
    __syncthreads();
    if (tid == 0) {
        int obs = atomicAdd(&g_fobs, 1);
        if (obs == NFIN - 1) {
            atomicExch(&g_done, 0);
            atomicExch(&g_all, 0);
            atomicExch(&g_fobs, 0);
        }
    }
}

extern "C" void kernel_launch(void* const* d_in, const int* in_sizes, int n_in,
                              void* d_out, int out_size) {
    const float* params = (const float*)d_in[0];
    const float* W1     = (const float*)d_in[1];
    const float* b1     = (const float*)d_in[2];
    const float* ln_g   = (const float*)d_in[3];
    const float* ln_b   = (const float*)d_in[4];
    const float* W2     = (const float*)d_in[5];
    const float* b2     = (const float*)d_in[6];
    float* out = (float*)d_out;

    fused_kernel<<<NPREP + NSCAN + NPAIR, IB>>>(params, W1, b1, ln_g, ln_b, W2, b2, out);
}